// round 10
// baseline (speedup 1.0000x reference)
#include <cuda_runtime.h>
#include <math.h>

#define B_DIM 64
#define C_DIM 80
#define T_DIM 16384
#define NTHREADS 256
#define NWARPS 8
#define CAP 2048             // per-quantile candidate capacity
#define FULL 0xFFFFFFFFu

// order-preserving float <-> u32 key (exact total order incl. ties/-0)
__device__ __forceinline__ unsigned f2k(float f) {
    unsigned u = __float_as_uint(f);
    return u ^ ((unsigned)((int)u >> 31) | 0x80000000u);
}
__device__ __forceinline__ float k2f(unsigned k) {
    unsigned m = (k & 0x80000000u) ? 0x80000000u : 0xFFFFFFFFu;
    return __uint_as_float(k ^ m);
}

__global__ void __launch_bounds__(NTHREADS, 8)
statpool_kernel(const float* __restrict__ x, const int* __restrict__ lengths,
                float* __restrict__ out) {
    extern __shared__ unsigned list[];   // [3 * CAP]

    __shared__ float red_s[NWARPS], red_s2[NWARPS];
    __shared__ int s_k[6];               // global target ranks (k, k+... per q)
    __shared__ float s_w[3];
    __shared__ unsigned s_klo[3], s_khi[3];  // bracket pivot keys
    __shared__ int s_cnt[3];             // appended candidates per quantile
    __shared__ unsigned s_base[3];       // count of elements with key < klo
    __shared__ unsigned s_keyout[6];

    const int row = blockIdx.x;
    const int b = row / C_DIM, c = row % C_DIM;
    const int n = lengths[b];
    const int tid = threadIdx.x, lane = tid & 31, warp = tid >> 5;

    if (tid < 3) { s_cnt[tid] = 0; s_base[tid] = 0u; }
    __syncthreads();

    // ---- pass 1: sum / sumsq only (pure FP + LDG) ----
    const float4* x4 = (const float4*)(x + (size_t)row * T_DIM);
    const int nfull = n >> 2;
    float sum = 0.f, sumsq = 0.f;
    for (int i = tid; i < nfull; i += NTHREADS) {
        float4 v = x4[i];
        sum += v.x + v.y + v.z + v.w;
        sumsq += v.x * v.x + v.y * v.y + v.z * v.z + v.w * v.w;
    }
    if (tid == 0) {                      // tail: at most 3 elements
        const float* xs = (const float*)x4;
        for (int t = nfull << 2; t < n; ++t) {
            float f = xs[t];
            sum += f; sumsq += f * f;
        }
    }
#pragma unroll
    for (int o = 16; o; o >>= 1) {
        sum += __shfl_down_sync(FULL, sum, o);
        sumsq += __shfl_down_sync(FULL, sumsq, o);
    }
    if (lane == 0) { red_s[warp] = sum; red_s2[warp] = sumsq; }
    __syncthreads();

    if (tid == 0) {
        float s = 0.f, s2 = 0.f;
#pragma unroll
        for (int w = 0; w < NWARPS; ++w) { s += red_s[w]; s2 += red_s2[w]; }
        float fn = (float)n;
        float mean = s / fn;
        float var = fmaxf(s2 / fn - mean * mean, 1e-6f);
        float sd = sqrtf(var);
        out[b * (5 * C_DIM) + 0 * C_DIM + c] = mean;
        out[b * (5 * C_DIM) + 1 * C_DIM + c] = sd;

        // rank targets + interp weights
        float n1 = (float)(n - 1);
        const float qs[3] = {0.25f, 0.5f, 0.75f};
        const float zs[3] = {-0.6744898f, 0.0f, 0.6744898f};
        const float DELTA = 0.075f;
#pragma unroll
        for (int q = 0; q < 3; ++q) {
            float pos = qs[q] * n1;
            float flo = floorf(pos);
            s_k[2 * q]     = (int)flo;
            s_k[2 * q + 1] = (int)ceilf(pos);
            s_w[q] = pos - flo;
            // analytic bracket pivots (exactness guaranteed by verification
            // + fallback, not by these guesses)
            s_klo[q] = f2k(mean + (zs[q] - DELTA) * sd);
            s_khi[q] = f2k(mean + (zs[q] + DELTA) * sd);
        }
    }
    __syncthreads();

    // bracket keys into registers (uniform)
    unsigned klo0 = s_klo[0], khi0 = s_khi[0];
    unsigned klo1 = s_klo[1], khi1 = s_khi[1];
    unsigned klo2 = s_klo[2], khi2 = s_khi[2];

    // ---- pass 2: count-less (registers) + bracket compaction (rare appends) ----
    unsigned c0 = 0, c1 = 0, c2 = 0;
    for (int i = tid; i < nfull; i += NTHREADS) {
        float4 v = x4[i];
        float vv[4] = {v.x, v.y, v.z, v.w};
#pragma unroll
        for (int j = 0; j < 4; ++j) {
            unsigned key = f2k(vv[j]);
            bool l0 = key < klo0, h0 = key < khi0;
            bool l1 = key < klo1, h1 = key < khi1;
            bool l2 = key < klo2, h2 = key < khi2;
            c0 += l0; c1 += l1; c2 += l2;
            if (h0 && !l0) { int p = atomicAdd(&s_cnt[0], 1); if (p < CAP) list[p] = key; }
            if (h1 && !l1) { int p = atomicAdd(&s_cnt[1], 1); if (p < CAP) list[CAP + p] = key; }
            if (h2 && !l2) { int p = atomicAdd(&s_cnt[2], 1); if (p < CAP) list[2 * CAP + p] = key; }
        }
    }
    if (tid == 0) {                      // tail
        const float* xs = (const float*)x4;
        for (int t = nfull << 2; t < n; ++t) {
            unsigned key = f2k(xs[t]);
            bool l0 = key < klo0, h0 = key < khi0;
            bool l1 = key < klo1, h1 = key < khi1;
            bool l2 = key < klo2, h2 = key < khi2;
            c0 += l0; c1 += l1; c2 += l2;
            if (h0 && !l0) { int p = atomicAdd(&s_cnt[0], 1); if (p < CAP) list[p] = key; }
            if (h1 && !l1) { int p = atomicAdd(&s_cnt[1], 1); if (p < CAP) list[CAP + p] = key; }
            if (h2 && !l2) { int p = atomicAdd(&s_cnt[2], 1); if (p < CAP) list[2 * CAP + p] = key; }
        }
    }
    // reduce count-less across block
#pragma unroll
    for (int o = 16; o; o >>= 1) {
        c0 += __shfl_down_sync(FULL, c0, o);
        c1 += __shfl_down_sync(FULL, c1, o);
        c2 += __shfl_down_sync(FULL, c2, o);
    }
    if (lane == 0) {
        atomicAdd(&s_base[0], c0);
        atomicAdd(&s_base[1], c1);
        atomicAdd(&s_base[2], c2);
    }
    __syncthreads();

    // ---- selection: warp j resolves target j (j = 2q + {lo,hi}) ----
    if (warp < 6) {
        const int q = warp >> 1;
        const int k = s_k[warp];
        const int base = (int)s_base[q];
        const int cnt = s_cnt[q];
        const int krem = k - base;
        const bool ok = (cnt <= CAP) && (krem >= 0) && (krem < cnt);

        if (ok) {
            // exact 32-step key bisection within the candidate list
            const unsigned* L = list + q * CAP;
            unsigned prefix = 0u;
            for (int bit = 31; bit >= 0; --bit) {
                unsigned cand = prefix | (1u << bit);
                unsigned cc = 0;
                for (int i2 = lane; i2 < cnt; i2 += 32)
                    cc += (L[i2] < cand) ? 1u : 0u;
#pragma unroll
                for (int o = 16; o; o >>= 1) cc += __shfl_down_sync(FULL, cc, o);
                cc = __shfl_sync(FULL, cc, 0);
                if (cc <= (unsigned)krem) prefix = cand;
            }
            if (lane == 0) s_keyout[warp] = prefix;
        } else {
            // fallback: exact 32-step key bisection over the full global row
            const float* xs = (const float*)x4;
            unsigned prefix = 0u;
            for (int bit = 31; bit >= 0; --bit) {
                unsigned cand = prefix | (1u << bit);
                unsigned cc = 0;
                for (int i2 = lane; i2 < T_DIM; i2 += 32)
                    if (i2 < n) cc += (f2k(xs[i2]) < cand) ? 1u : 0u;
#pragma unroll
                for (int o = 16; o; o >>= 1) cc += __shfl_down_sync(FULL, cc, o);
                cc = __shfl_sync(FULL, cc, 0);
                if (cc <= (unsigned)k) prefix = cand;
            }
            if (lane == 0) s_keyout[warp] = prefix;
        }
    }
    __syncthreads();

    // ---- quantile interpolation + writeback ----
    if (tid < 3) {
        float vlo = k2f(s_keyout[2 * tid]);
        float vhi = k2f(s_keyout[2 * tid + 1]);
        out[b * (5 * C_DIM) + (2 + tid) * C_DIM + c] = vlo + s_w[tid] * (vhi - vlo);
    }
}

extern "C" void kernel_launch(void* const* d_in, const int* in_sizes, int n_in,
                              void* d_out, int out_size) {
    const float* x;
    const int* lengths;
    if (in_sizes[0] == B_DIM) {
        lengths = (const int*)d_in[0];
        x = (const float*)d_in[1];
    } else {
        x = (const float*)d_in[0];
        lengths = (const int*)d_in[1];
    }
    float* out = (float*)d_out;

    size_t smem = (size_t)3 * CAP * sizeof(unsigned);  // 24 KB -> 8 CTAs/SM
    cudaFuncSetAttribute(statpool_kernel,
                         cudaFuncAttributeMaxDynamicSharedMemorySize, (int)smem);
    statpool_kernel<<<B_DIM * C_DIM, NTHREADS, smem>>>(x, lengths, out);
}

// round 11
// speedup vs baseline: 2.0707x; 2.0707x over previous
#include <cuda_runtime.h>
#include <math.h>

#define B_DIM 64
#define C_DIM 80
#define T_DIM 16384
#define NTHREADS 256
#define NWARPS 8
#define NBIN 1024
#define NWORD (T_DIM / 4)    // packed coarse-byte words
#define CAP_G 256            // per-group candidate capacity (expected ~51 used)
#define FULL 0xFFFFFFFFu

// order-preserving float <-> u32 key (exact total order incl. ties/-0)
__device__ __forceinline__ unsigned f2k(float f) {
    unsigned u = __float_as_uint(f);
    return u ^ ((unsigned)((int)u >> 31) | 0x80000000u);
}
__device__ __forceinline__ float k2f(unsigned k) {
    unsigned m = (k & 0x80000000u) ? 0x80000000u : 0xFFFFFFFFu;
    return __uint_as_float(k ^ m);
}

// value-linear bin: 1024 bins across [-4, 4]; clamped; monotone in f
__device__ __forceinline__ int vbin(float f) {
    int bi = __float2int_rd(fmaf(f, 128.0f, 512.0f));
    return max(0, min(NBIN - 1, bi));
}

__global__ void __launch_bounds__(NTHREADS, 8)
statpool_kernel(const float* __restrict__ x, const int* __restrict__ lengths,
                float* __restrict__ out) {
    extern __shared__ unsigned sh[];
    unsigned* bwords = sh;                    // [4096]  packed coarse bytes (16 KB)
    unsigned* hist = sh + NWORD;              // [1024]
    unsigned* list = hist + NBIN;             // [6 * CAP_G]

    __shared__ float red_s[NWARPS], red_s2[NWARPS];
    __shared__ unsigned wtot[NWARPS], wbase[NWARPS];
    __shared__ unsigned s_k[6];
    __shared__ float s_w[3];
    __shared__ int s_bin[6];
    __shared__ unsigned s_krem[6];
    __shared__ int s_g[6];
    __shared__ int s_ubin[6];                 // distinct exact bins (-1 pad)
    __shared__ unsigned s_cb[6];              // distinct coarse bytes, replicated x4
    __shared__ int s_ncb;
    __shared__ int s_gcnt[6];
    __shared__ unsigned s_keyout[6];

    const int row = blockIdx.x;
    const int b = row / C_DIM, c = row % C_DIM;
    const int n = lengths[b];
    const int tid = threadIdx.x, lane = tid & 31, warp = tid >> 5;

    for (int i = tid; i < NBIN; i += NTHREADS) hist[i] = 0u;
    if (tid < 6) { s_gcnt[tid] = 0; s_ubin[tid] = -1; }
    __syncthreads();

    // ---- pass 1: sum/sumsq + 1024-bin histogram + packed coarse-byte cache ----
    const float* xrow = x + (size_t)row * T_DIM;
    const float4* x4 = (const float4*)xrow;
    const int nfull = n >> 2;
    float sum = 0.f, sumsq = 0.f;
    for (int i = tid; i < nfull; i += NTHREADS) {
        float4 v = x4[i];
        sum += v.x + v.y + v.z + v.w;
        sumsq = fmaf(v.x, v.x, sumsq); sumsq = fmaf(v.y, v.y, sumsq);
        sumsq = fmaf(v.z, v.z, sumsq); sumsq = fmaf(v.w, v.w, sumsq);
        int b0 = vbin(v.x), b1 = vbin(v.y), b2 = vbin(v.z), b3 = vbin(v.w);
        atomicAdd(&hist[b0], 1u);
        atomicAdd(&hist[b1], 1u);
        atomicAdd(&hist[b2], 1u);
        atomicAdd(&hist[b3], 1u);
        bwords[i] = (unsigned)(b0 >> 2) | ((unsigned)(b1 >> 2) << 8) |
                    ((unsigned)(b2 >> 2) << 16) | ((unsigned)(b3 >> 2) << 24);
    }
    if (tid == 0 && (n & 3)) {               // tail word: <=3 valid elements
        unsigned pw = 0u;
        for (int t = nfull << 2; t < n; ++t) {
            float f = xrow[t];
            sum += f; sumsq = fmaf(f, f, sumsq);
            int bi = vbin(f);
            atomicAdd(&hist[bi], 1u);
            pw |= (unsigned)(bi >> 2) << (8 * (t & 3));
        }
        bwords[nfull] = pw;                  // stale bytes impossible: fresh write
    }

    // ---- block reduce sums ----
#pragma unroll
    for (int o = 16; o; o >>= 1) {
        sum += __shfl_down_sync(FULL, sum, o);
        sumsq += __shfl_down_sync(FULL, sumsq, o);
    }
    if (lane == 0) { red_s[warp] = sum; red_s2[warp] = sumsq; }
    __syncthreads();

    // ---- inclusive scan of hist: thread owns 4 consecutive bins ----
    unsigned vb[4], loc = 0;
#pragma unroll
    for (int d = 0; d < 4; ++d) { vb[d] = hist[tid * 4 + d]; loc += vb[d]; }
    unsigned inc = loc;
#pragma unroll
    for (int o = 1; o < 32; o <<= 1) {
        unsigned t = __shfl_up_sync(FULL, inc, o);
        if (lane >= o) inc += t;
    }
    if (lane == 31) wtot[warp] = inc;
    __syncthreads();

    if (warp == 0) {
        unsigned t = (lane < NWARPS) ? wtot[lane] : 0u;
        unsigned ti = t;
#pragma unroll
        for (int o = 1; o < NWARPS; o <<= 1) {
            unsigned u = __shfl_up_sync(FULL, ti, o);
            if (lane >= o) ti += u;
        }
        if (lane < NWARPS) wbase[lane] = ti - t;
    } else if (tid == 32) {
        // mean/std + rank targets (concurrent with warp 0)
        float s = 0.f, s2 = 0.f;
#pragma unroll
        for (int w = 0; w < NWARPS; ++w) { s += red_s[w]; s2 += red_s2[w]; }
        float fn = (float)n;
        float mean = s / fn;
        float var = fmaxf(s2 / fn - mean * mean, 1e-6f);
        out[b * (5 * C_DIM) + 0 * C_DIM + c] = mean;
        out[b * (5 * C_DIM) + 1 * C_DIM + c] = sqrtf(var);
        float n1 = (float)(n - 1);
        const float qs[3] = {0.25f, 0.5f, 0.75f};
#pragma unroll
        for (int q = 0; q < 3; ++q) {
            float pos = qs[q] * n1;
            float flo = floorf(pos);
            s_k[2 * q]     = (unsigned)(int)flo;
            s_k[2 * q + 1] = (unsigned)(int)ceilf(pos);
            s_w[q] = pos - flo;
        }
    }
    __syncthreads();

    unsigned run = wbase[warp] + (inc - loc);
#pragma unroll
    for (int d = 0; d < 4; ++d) { run += vb[d]; hist[tid * 4 + d] = run; }
    __syncthreads();

    // ---- locate bin per target (6 threads bsearch on cumsum) ----
    if (tid < 6) {
        unsigned k = s_k[tid];
        int lo = 0, hi = NBIN - 1;
        while (lo < hi) {
            int mid = (lo + hi) >> 1;
            if (hist[mid] > k) hi = mid; else lo = mid + 1;
        }
        s_bin[tid] = lo;
        s_krem[tid] = k - (lo ? hist[lo - 1] : 0u);
    }
    __syncthreads();

    // ---- dedup exact bins + coarse bytes ----
    if (tid == 0) {
        int ng = 0;
        int ubin[6];
#pragma unroll
        for (int j = 0; j < 6; ++j) {
            int p = s_bin[j];
            int g = -1;
            for (int g2 = 0; g2 < ng; ++g2) if (ubin[g2] == p) { g = g2; break; }
            if (g < 0) { g = ng; ubin[ng++] = p; s_ubin[g] = p; }
            s_g[j] = g;
        }
        int ncb = 0;
        unsigned cbs[6];
        for (int g = 0; g < ng; ++g) {
            unsigned cb = (unsigned)(ubin[g] >> 2);
            bool found = false;
            for (int g2 = 0; g2 < ncb; ++g2) if (cbs[g2] == cb) { found = true; break; }
            if (!found) cbs[ncb++] = cb;
        }
        for (int g = 0; g < ncb; ++g) s_cb[g] = cbs[g] * 0x01010101u;
        s_ncb = ncb;
    }
    __syncthreads();

    // uniform broadcast of match tables into registers
    int ub[6];
#pragma unroll
    for (int g = 0; g < 6; ++g) ub[g] = s_ubin[g];
    const int ncb = s_ncb;

    // ---- pass 2: SIMD byte scan of the bin cache; rare exact-check reloads ----
    const int W = (n + 3) >> 2;
    for (int w = tid; w < W; w += NTHREADS) {
        unsigned pw = bwords[w];
        unsigned m = 0u;
        for (int g = 0; g < ncb; ++g) m |= __vcmpeq4(pw, s_cb[g]);
        if (m) {
#pragma unroll
            for (int j = 0; j < 4; ++j) {
                if (m & (0xFFu << (8 * j))) {
                    int t = (w << 2) + j;
                    if (t < n) {
                        float f = xrow[t];          // scattered, L2-hot
                        int bi = vbin(f);
                        int g = 0;
#pragma unroll
                        for (int g2 = 0; g2 < 6; ++g2) if (bi == ub[g2]) g = g2 + 1;
                        if (g) {
                            int pos = atomicAdd(&s_gcnt[g - 1], 1);
                            if (pos < CAP_G) list[(g - 1) * CAP_G + pos] = f2k(f);
                        }
                    }
                }
            }
        }
    }
    __syncthreads();

    // ---- exact selection: warp j resolves target j ----
    if (warp < 6) {
        const int g = s_g[warp];
        const int cnt = s_gcnt[g];
        const unsigned kk = s_krem[warp];

        if (cnt <= CAP_G) {
            // stable-rank brute force over small candidate list (m ~ 51)
            const unsigned* L = list + g * CAP_G;
            const int m = cnt;
            for (int base = 0; base < m; base += 32) {
                int idx = base + lane;
                unsigned e = (idx < m) ? L[idx] : 0xFFFFFFFFu;
                unsigned cl = 0, ce = 0;
                for (int t = 0; t < m; ++t) {
                    unsigned o = L[t];              // broadcast read
                    cl += (o < e);
                    ce += (o == e && t < idx);
                }
                if (idx < m && cl + ce == kk) s_keyout[warp] = e;
            }
        } else {
            // adversarial fallback: exact 32-step key bisection over global row
            const unsigned kglob = s_k[warp];
            unsigned prefix = 0u;
            for (int bit = 31; bit >= 0; --bit) {
                unsigned cand = prefix | (1u << bit);
                unsigned cc = 0;
                for (int i2 = lane; i2 < T_DIM; i2 += 32)
                    if (i2 < n) cc += (f2k(xrow[i2]) < cand) ? 1u : 0u;
#pragma unroll
                for (int o = 16; o; o >>= 1) cc += __shfl_down_sync(FULL, cc, o);
                cc = __shfl_sync(FULL, cc, 0);
                if (cc <= kglob) prefix = cand;
            }
            if (lane == 0) s_keyout[warp] = prefix;
        }
    }
    __syncthreads();

    // ---- quantile interpolation + writeback ----
    if (tid < 3) {
        float vlo = k2f(s_keyout[2 * tid]);
        float vhi = k2f(s_keyout[2 * tid + 1]);
        out[b * (5 * C_DIM) + (2 + tid) * C_DIM + c] = vlo + s_w[tid] * (vhi - vlo);
    }
}

extern "C" void kernel_launch(void* const* d_in, const int* in_sizes, int n_in,
                              void* d_out, int out_size) {
    const float* x;
    const int* lengths;
    if (in_sizes[0] == B_DIM) {
        lengths = (const int*)d_in[0];
        x = (const float*)d_in[1];
    } else {
        x = (const float*)d_in[0];
        lengths = (const int*)d_in[1];
    }
    float* out = (float*)d_out;

    // 16 KB bytes + 4 KB hist + 6 KB lists = 26 KB -> 8 CTAs/SM
    size_t smem = (size_t)(NWORD + NBIN + 6 * CAP_G) * sizeof(unsigned);
    cudaFuncSetAttribute(statpool_kernel,
                         cudaFuncAttributeMaxDynamicSharedMemorySize, (int)smem);
    statpool_kernel<<<B_DIM * C_DIM, NTHREADS, smem>>>(x, lengths, out);
}

// round 12
// speedup vs baseline: 2.4610x; 1.1885x over previous
#include <cuda_runtime.h>
#include <math.h>

#define B_DIM 64
#define C_DIM 80
#define T_DIM 16384
#define NTHREADS 256
#define NWARPS 8
#define CAP 2048
#define HBIN 256
#define NHIST (3 * HBIN)
#define BINBUF 32
#define FULL 0xFFFFFFFFu

// order-preserving float <-> u32 key (exact total order incl. ties/-0)
__device__ __forceinline__ unsigned f2k(float f) {
    unsigned u = __float_as_uint(f);
    return u ^ ((unsigned)((int)u >> 31) | 0x80000000u);
}
__device__ __forceinline__ float k2f(unsigned k) {
    unsigned m = (k & 0x80000000u) ? 0x80000000u : 0xFFFFFFFFu;
    return __uint_as_float(k ^ m);
}

__global__ void __launch_bounds__(NTHREADS, 8)
statpool_kernel(const float* __restrict__ x, const int* __restrict__ lengths,
                float* __restrict__ out) {
    __shared__ float list[CAP];          // merged in-bracket candidates (floats)
    __shared__ unsigned hist[NHIST];     // 3 brackets x 256 bins -> cumsum
    __shared__ float red_s[NWARPS], red_s2[NWARPS];
    __shared__ unsigned wtot[NWARPS], wbase[NWARPS];
    __shared__ int s_k[6];               // global target ranks
    __shared__ float s_w[3];
    __shared__ float s_lo[3], s_hi[3], s_scale[3];
    __shared__ int s_bad;                // degenerate bracket width -> fallback
    __shared__ int s_below[3];           // exact count of f < lo_q
    __shared__ int s_cnt;                // merged candidate count
    __shared__ int s_tbin[6], s_kib[6], s_m[6], s_ok[6];
    __shared__ unsigned binbuf[6 * BINBUF];
    __shared__ int bcnt[6];
    __shared__ unsigned s_keyout[6];

    const int row = blockIdx.x;
    const int b = row / C_DIM, c = row % C_DIM;
    const int n = lengths[b];
    const int tid = threadIdx.x, lane = tid & 31, warp = tid >> 5;

    // ---- init shared state ----
    for (int i = tid; i < NHIST; i += NTHREADS) hist[i] = 0u;
    if (tid < 6) bcnt[tid] = 0;
    if (tid < 3) s_below[tid] = 0;
    if (tid == 0) { s_cnt = 0; s_bad = 0; }

    // ---- pass 1: sum / sumsq (LDG + FP only) ----
    const float* xrow = x + (size_t)row * T_DIM;
    const float4* x4 = (const float4*)xrow;
    const int nfull = n >> 2;
    float sum = 0.f, sumsq = 0.f;
    for (int i = tid; i < nfull; i += NTHREADS) {
        float4 v = x4[i];
        sum += v.x + v.y + v.z + v.w;
        sumsq = fmaf(v.x, v.x, sumsq); sumsq = fmaf(v.y, v.y, sumsq);
        sumsq = fmaf(v.z, v.z, sumsq); sumsq = fmaf(v.w, v.w, sumsq);
    }
    if (tid == 0) {
        for (int t = nfull << 2; t < n; ++t) {
            float f = xrow[t];
            sum += f; sumsq = fmaf(f, f, sumsq);
        }
    }
#pragma unroll
    for (int o = 16; o; o >>= 1) {
        sum += __shfl_down_sync(FULL, sum, o);
        sumsq += __shfl_down_sync(FULL, sumsq, o);
    }
    if (lane == 0) { red_s[warp] = sum; red_s2[warp] = sumsq; }
    __syncthreads();

    if (tid == 0) {
        float s = 0.f, s2 = 0.f;
#pragma unroll
        for (int w = 0; w < NWARPS; ++w) { s += red_s[w]; s2 += red_s2[w]; }
        float fn = (float)n;
        float mean = s / fn;
        float var = fmaxf(s2 / fn - mean * mean, 1e-6f);
        float sd = sqrtf(var);
        out[b * (5 * C_DIM) + 0 * C_DIM + c] = mean;
        out[b * (5 * C_DIM) + 1 * C_DIM + c] = sd;

        float n1 = (float)(n - 1);
        const float qs[3] = {0.25f, 0.5f, 0.75f};
        const float zs[3] = {-0.6744898f, 0.0f, 0.6744898f};
        const float DLT = 0.04f;
        int bad = 0;
#pragma unroll
        for (int q = 0; q < 3; ++q) {
            float pos = qs[q] * n1;
            float flo = floorf(pos);
            s_k[2 * q]     = (int)flo;
            s_k[2 * q + 1] = (int)ceilf(pos);
            s_w[q] = pos - flo;
            float lo = mean + (zs[q] - DLT) * sd;
            float hi = mean + (zs[q] + DLT) * sd;
            s_lo[q] = lo; s_hi[q] = hi;
            float wdt = hi - lo;
            if (!(wdt > 0.f)) { bad = 1; wdt = 1.f; }
            s_scale[q] = (float)HBIN / wdt;
        }
        s_bad = bad;
    }
    __syncthreads();

    // ---- pass 2: exact below-lo counts + merged bracket compaction ----
    const float lo0 = s_lo[0], lo1 = s_lo[1], lo2 = s_lo[2];
    const float hi0 = s_hi[0], hi1 = s_hi[1], hi2 = s_hi[2];
    int c0 = 0, c1 = 0, c2 = 0;
    for (int i = tid; i < nfull; i += NTHREADS) {
        float4 v = x4[i];
        bool i0, i1, i2, i3;
        {
            bool l0 = v.x < lo0, l1 = v.x < lo1, l2 = v.x < lo2;
            c0 += l0; c1 += l1; c2 += l2;
            i0 = (!l0 & (v.x < hi0)) | (!l1 & (v.x < hi1)) | (!l2 & (v.x < hi2));
        }
        {
            bool l0 = v.y < lo0, l1 = v.y < lo1, l2 = v.y < lo2;
            c0 += l0; c1 += l1; c2 += l2;
            i1 = (!l0 & (v.y < hi0)) | (!l1 & (v.y < hi1)) | (!l2 & (v.y < hi2));
        }
        {
            bool l0 = v.z < lo0, l1 = v.z < lo1, l2 = v.z < lo2;
            c0 += l0; c1 += l1; c2 += l2;
            i2 = (!l0 & (v.z < hi0)) | (!l1 & (v.z < hi1)) | (!l2 & (v.z < hi2));
        }
        {
            bool l0 = v.w < lo0, l1 = v.w < lo1, l2 = v.w < lo2;
            c0 += l0; c1 += l1; c2 += l2;
            i3 = (!l0 & (v.w < hi0)) | (!l1 & (v.w < hi1)) | (!l2 & (v.w < hi2));
        }
        int h = (int)i0 + (int)i1 + (int)i2 + (int)i3;
        if (h) {                         // one atomic covers all 4 slots
            int p = atomicAdd(&s_cnt, h);
            if (i0) { if (p < CAP) list[p] = v.x; p++; }
            if (i1) { if (p < CAP) list[p] = v.y; p++; }
            if (i2) { if (p < CAP) list[p] = v.z; p++; }
            if (i3) { if (p < CAP) list[p] = v.w; p++; }
        }
    }
    if (tid == 0) {                      // tail: <=3 elements
        for (int t = nfull << 2; t < n; ++t) {
            float f = xrow[t];
            bool l0 = f < lo0, l1 = f < lo1, l2 = f < lo2;
            c0 += l0; c1 += l1; c2 += l2;
            bool in = (!l0 & (f < hi0)) | (!l1 & (f < hi1)) | (!l2 & (f < hi2));
            if (in) { int p = atomicAdd(&s_cnt, 1); if (p < CAP) list[p] = f; }
        }
    }
#pragma unroll
    for (int o = 16; o; o >>= 1) {
        c0 += __shfl_down_sync(FULL, c0, o);
        c1 += __shfl_down_sync(FULL, c1, o);
        c2 += __shfl_down_sync(FULL, c2, o);
    }
    if (lane == 0) {
        atomicAdd(&s_below[0], c0);
        atomicAdd(&s_below[1], c1);
        atomicAdd(&s_below[2], c2);
    }
    __syncthreads();

    const int cnt = min(s_cnt, CAP);
    const int ovf = (s_cnt > CAP) | s_bad;

    // ---- phase 3a: mini-histogram over candidates only ----
    for (int i = tid; i < cnt; i += NTHREADS) {
        float f = list[i];
        int q = (int)(f >= lo1) + (int)(f >= lo2);   // brackets disjoint
        int bin = (int)((f - s_lo[q]) * s_scale[q]);
        bin = max(0, min(HBIN - 1, bin));
        atomicAdd(&hist[q * HBIN + bin], 1u);
    }
    __syncthreads();

    // ---- phase 3b: inclusive scan of 768 bins (thread owns 3) ----
    unsigned h0 = hist[tid * 3], h1 = hist[tid * 3 + 1], h2 = hist[tid * 3 + 2];
    unsigned loc = h0 + h1 + h2;
    unsigned incv = loc;
#pragma unroll
    for (int o = 1; o < 32; o <<= 1) {
        unsigned t = __shfl_up_sync(FULL, incv, o);
        if (lane >= o) incv += t;
    }
    if (lane == 31) wtot[warp] = incv;
    __syncthreads();
    if (warp == 0) {
        unsigned t = (lane < NWARPS) ? wtot[lane] : 0u;
        unsigned ti = t;
#pragma unroll
        for (int o = 1; o < NWARPS; o <<= 1) {
            unsigned u = __shfl_up_sync(FULL, ti, o);
            if (lane >= o) ti += u;
        }
        if (lane < NWARPS) wbase[lane] = ti - t;
    }
    __syncthreads();
    unsigned run = wbase[warp] + (incv - loc);
    run += h0; hist[tid * 3] = run;
    run += h1; hist[tid * 3 + 1] = run;
    run += h2; hist[tid * 3 + 2] = run;
    __syncthreads();

    // ---- phase 3c: locate bin per target (6 threads) ----
    if (tid < 6) {
        const int q = tid >> 1;
        const int base = q ? (int)hist[q * HBIN - 1] : 0;
        const int total = (int)hist[q * HBIN + HBIN - 1] - base;
        const int krem = s_k[tid] - s_below[q];
        int ok = !ovf && krem >= 0 && krem < total;
        if (ok) {
            const int CU = krem + base;          // target in global-cum domain
            int lo = q * HBIN, hi = q * HBIN + HBIN - 1;
            while (lo < hi) {
                int mid = (lo + hi) >> 1;
                if ((int)hist[mid] > CU) hi = mid; else lo = mid + 1;
            }
            int prev = (lo > q * HBIN) ? (int)hist[lo - 1] : base;
            int m = (int)hist[lo] - prev;
            if (m > BINBUF) ok = 0;              // rare tie-pileup -> fallback
            s_tbin[tid] = lo;
            s_kib[tid] = CU - prev;
            s_m[tid] = m;
        }
        s_ok[tid] = ok;
    }
    __syncthreads();

    // ---- phase 3d: selection, warp j resolves target j ----
    if (warp < 6) {
        if (s_ok[warp]) {
            const int tb = s_tbin[warp];
            // collect this bin's candidates (no warp collectives -> safe)
            for (int i = lane; i < cnt; i += 32) {
                float f = list[i];
                int q = (int)(f >= lo1) + (int)(f >= lo2);
                int bin = (int)((f - s_lo[q]) * s_scale[q]);
                bin = max(0, min(HBIN - 1, bin)) + q * HBIN;
                if (bin == tb) {
                    int p = atomicAdd(&bcnt[warp], 1);
                    if (p < BINBUF) binbuf[warp * BINBUF + p] = f2k(f);
                }
            }
            __syncwarp();
            // exact stable-rank among m (<=32) keys; uniform trip count
            const int m = s_m[warp];
            const int kib = s_kib[warp];
            unsigned e = (lane < m) ? binbuf[warp * BINBUF + lane] : 0xFFFFFFFFu;
            int cl = 0, ce = 0;
            for (int t = 0; t < m; ++t) {
                unsigned o = binbuf[warp * BINBUF + t];   // broadcast read
                cl += (o < e);
                ce += (o == e && t < lane);
            }
            if (lane < m && cl + ce == kib) s_keyout[warp] = e;
        } else {
            // exact fallback: 32-step key bisection over full global row
            const int kglob = s_k[warp];
            unsigned prefix = 0u;
            for (int bit = 31; bit >= 0; --bit) {
                unsigned cand = prefix | (1u << bit);
                unsigned cc = 0;
                for (int i2 = lane; i2 < T_DIM; i2 += 32)
                    if (i2 < n) cc += (f2k(xrow[i2]) < cand) ? 1u : 0u;
#pragma unroll
                for (int o = 16; o; o >>= 1) cc += __shfl_down_sync(FULL, cc, o);
                cc = __shfl_sync(FULL, cc, 0);
                if (cc <= (unsigned)kglob) prefix = cand;
            }
            if (lane == 0) s_keyout[warp] = prefix;
        }
    }
    __syncthreads();

    // ---- quantile interpolation + writeback ----
    if (tid < 3) {
        float vlo = k2f(s_keyout[2 * tid]);
        float vhi = k2f(s_keyout[2 * tid + 1]);
        out[b * (5 * C_DIM) + (2 + tid) * C_DIM + c] = vlo + s_w[tid] * (vhi - vlo);
    }
}

extern "C" void kernel_launch(void* const* d_in, const int* in_sizes, int n_in,
                              void* d_out, int out_size) {
    const float* x;
    const int* lengths;
    if (in_sizes[0] == B_DIM) {
        lengths = (const int*)d_in[0];
        x = (const float*)d_in[1];
    } else {
        x = (const float*)d_in[0];
        lengths = (const int*)d_in[1];
    }
    float* out = (float*)d_out;

    statpool_kernel<<<B_DIM * C_DIM, NTHREADS>>>(x, lengths, out);
}